// round 14
// baseline (speedup 1.0000x reference)
#include <cuda_runtime.h>

#define NN   50000
#define EE   800000
#define DF   128
#define NCLS 3
#define MQ   10000
#define C0   25088   // chunk boundary: 196 GEMM blocks * 128 rows

// Scratch (static device globals — no runtime allocation).
__device__ __align__(16) float g_Ha[(size_t)NN * DF];
__device__ __align__(16) float g_Hb[(size_t)NN * DF];
__device__ __align__(16) float g_A [(size_t)NN * DF];
__device__ __align__(16) float g_logits[(size_t)NN * NCLS];
__device__ int g_deg[NN];
__device__ int g_off[NN];
__device__ int g_rank[EE];
__device__ int g_csr[EE];

// Side stream + events, created at static-init.
struct SideStream {
    cudaStream_t s;
    cudaEvent_t  fork, join, a0, b0, a1, b1;
    SideStream() {
        cudaStreamCreateWithFlags(&s, cudaStreamNonBlocking);
        cudaEventCreateWithFlags(&fork, cudaEventDisableTiming);
        cudaEventCreateWithFlags(&join, cudaEventDisableTiming);
        cudaEventCreateWithFlags(&a0, cudaEventDisableTiming);
        cudaEventCreateWithFlags(&b0, cudaEventDisableTiming);
        cudaEventCreateWithFlags(&a1, cudaEventDisableTiming);
        cudaEventCreateWithFlags(&b1, cudaEventDisableTiming);
    }
};
static SideStream g_side;

// ---------------------------------------------------------------------------
// Packed f32x2 helpers (Blackwell sm_100a+)
// ---------------------------------------------------------------------------
__device__ __forceinline__ unsigned long long splat2(float v)
{
    unsigned long long r;
    asm("mov.b64 %0, {%1, %1};" : "=l"(r) : "f"(v));
    return r;
}
__device__ __forceinline__ void fma2(unsigned long long& d,
                                     unsigned long long a, unsigned long long b)
{
    asm("fma.rn.f32x2 %0, %1, %2, %0;" : "+l"(d) : "l"(a), "l"(b));
}
__device__ __forceinline__ void unpack2(unsigned long long v, float& lo, float& hi)
{
    asm("mov.b64 {%0, %1}, %2;" : "=f"(lo), "=f"(hi) : "l"(v));
}

// ---------------------------------------------------------------------------
// CSR build: memset(deg) -> histogram(dst) capturing per-edge rank -> scan ->
// fill (NO atomics in fill: position = off[dst] + rank[e])
// ---------------------------------------------------------------------------
__global__ void hist_kernel(const int* __restrict__ edges)
{
    int e = blockIdx.x * blockDim.x + threadIdx.x;
    if (e >= EE) return;
    int dst = edges[EE + e];
    int r = 0;
    if ((unsigned)dst < NN) r = atomicAdd(&g_deg[dst], 1);
    g_rank[e] = r;
}

__global__ void __launch_bounds__(1024) scan_kernel()
{
    __shared__ int sh[1024];
    const int T = 1024;
    const int CH = (NN + T - 1) / T;          // 49
    int t = threadIdx.x;
    int start = t * CH;
    int end   = min(start + CH, NN);

    int s = 0;
    for (int i = start; i < end; i++) s += g_deg[i];
    sh[t] = s;
    __syncthreads();

    for (int off = 1; off < T; off <<= 1) {
        int v = (t >= off) ? sh[t - off] : 0;
        __syncthreads();
        sh[t] += v;
        __syncthreads();
    }
    int run = sh[t] - s;   // exclusive prefix for this thread's chunk
    for (int i = start; i < end; i++) {
        g_off[i] = run;
        run += g_deg[i];
    }
}

__global__ void fill_kernel(const int* __restrict__ edges)
{
    int e = blockIdx.x * blockDim.x + threadIdx.x;
    if (e >= EE) return;
    int dst = edges[EE + e];
    int src = edges[e];
    if ((unsigned)dst >= NN || (unsigned)src >= NN) return;
    g_csr[g_off[dst] + g_rank[e]] = src;
}

// ---------------------------------------------------------------------------
// GEMM (R10 config): H[r][n] = sum_k act(X[r][k]) * W[n][k] + b[n]
// BM=128, BN=128, BK=32; 256 threads; 8x8 tile, packed f32x2 FMAs; B tile in
// two conflict-free half-tiles; __launch_bounds__(256,2). row_base for chunks.
// ---------------------------------------------------------------------------
#define LDP  132
#define LDPW 68

template <bool RELU_IN>
__global__ void __launch_bounds__(256, 2) gemm_kernel(
    const float* __restrict__ X, const float* __restrict__ W,
    const float* __restrict__ bias, float* __restrict__ H, int row_base)
{
    __shared__ __align__(16) float Xs [32][LDP];
    __shared__ __align__(16) float WsA[32][LDPW];
    __shared__ __align__(16) float WsB[32][LDPW];

    const int tid  = threadIdx.x;
    const int row0 = row_base + blockIdx.x * 128;
    const int tr   = tid >> 4;
    const int tc   = tid & 15;

    unsigned long long acc2[4][8];
    #pragma unroll
    for (int i = 0; i < 4; i++)
        #pragma unroll
        for (int j = 0; j < 8; j++) acc2[i][j] = 0ull;

    for (int kb = 0; kb < DF; kb += 32) {
        #pragma unroll
        for (int i = 0; i < 4; i++) {
            int idx = tid + i * 256;
            int r   = idx >> 3;
            int c4  = idx & 7;
            int gr  = row0 + r;
            float4 v = make_float4(0.f, 0.f, 0.f, 0.f);
            if (gr < NN)
                v = *reinterpret_cast<const float4*>(X + (size_t)gr * DF + kb + c4 * 4);
            if (RELU_IN) {
                v.x = fmaxf(v.x, 0.f); v.y = fmaxf(v.y, 0.f);
                v.z = fmaxf(v.z, 0.f); v.w = fmaxf(v.w, 0.f);
            }
            Xs[c4 * 4 + 0][r] = v.x; Xs[c4 * 4 + 1][r] = v.y;
            Xs[c4 * 4 + 2][r] = v.z; Xs[c4 * 4 + 3][r] = v.w;
        }
        #pragma unroll
        for (int i = 0; i < 4; i++) {
            int idx = tid + i * 256;
            int n   = idx >> 3;
            int c4  = idx & 7;
            float4 v = *reinterpret_cast<const float4*>(W + (size_t)n * DF + kb + c4 * 4);
            int grp = n >> 3;
            int c   = n & 7;
            float* dstcol = (c < 4) ? &WsA[0][grp * 4 + c] : &WsB[0][grp * 4 + (c - 4)];
            dstcol[(c4 * 4 + 0) * LDPW] = v.x;
            dstcol[(c4 * 4 + 1) * LDPW] = v.y;
            dstcol[(c4 * 4 + 2) * LDPW] = v.z;
            dstcol[(c4 * 4 + 3) * LDPW] = v.w;
        }
        __syncthreads();

        #pragma unroll
        for (int k = 0; k < 32; k++) {
            ulonglong2 a01 = *reinterpret_cast<const ulonglong2*>(&Xs[k][tr * 8]);
            ulonglong2 a23 = *reinterpret_cast<const ulonglong2*>(&Xs[k][tr * 8 + 4]);
            float4 n0 = *reinterpret_cast<const float4*>(&WsA[k][tc * 4]);
            float4 n1 = *reinterpret_cast<const float4*>(&WsB[k][tc * 4]);

            unsigned long long ap[4] = {a01.x, a01.y, a23.x, a23.y};
            unsigned long long bs[8];
            bs[0] = splat2(n0.x); bs[1] = splat2(n0.y);
            bs[2] = splat2(n0.z); bs[3] = splat2(n0.w);
            bs[4] = splat2(n1.x); bs[5] = splat2(n1.y);
            bs[6] = splat2(n1.z); bs[7] = splat2(n1.w);

            #pragma unroll
            for (int i = 0; i < 4; i++)
                #pragma unroll
                for (int j = 0; j < 8; j++)
                    fma2(acc2[i][j], ap[i], bs[j]);
        }
        __syncthreads();
    }

    float bn[8];
    #pragma unroll
    for (int j = 0; j < 8; j++) bn[j] = bias[tc * 8 + j];

    float accf[8][8];
    #pragma unroll
    for (int i2 = 0; i2 < 4; i2++)
        #pragma unroll
        for (int j = 0; j < 8; j++)
            unpack2(acc2[i2][j], accf[2 * i2][j], accf[2 * i2 + 1][j]);

    #pragma unroll
    for (int i = 0; i < 8; i++) {
        int gr = row0 + tr * 8 + i;
        if (gr < NN) {
            #pragma unroll
            for (int j = 0; j < 8; j += 4) {
                float4 v;
                v.x = accf[i][j + 0] + bn[j + 0];
                v.y = accf[i][j + 1] + bn[j + 1];
                v.z = accf[i][j + 2] + bn[j + 2];
                v.w = accf[i][j + 3] + bn[j + 3];
                *reinterpret_cast<float4*>(H + (size_t)gr * DF + tc * 8 + j) = v;
            }
        }
    }
}

// ---------------------------------------------------------------------------
// Gather segment-sum over node range: AGG[n] = H[n] + sum_{s in csr[n]} H[s].
// One warp per node.
// ---------------------------------------------------------------------------
__device__ __forceinline__ float4 gather_row(int node, int lane,
                                             const float* __restrict__ H)
{
    int start = g_off[node];
    int deg   = g_deg[node];

    float4 acc = *reinterpret_cast<const float4*>(H + (size_t)node * DF + lane * 4);

    for (int j = 0; j < deg; j += 32) {
        int rem  = deg - j;
        int cnt  = rem < 32 ? rem : 32;
        int myi  = (lane < cnt) ? g_csr[start + j + lane] : 0;
        #pragma unroll 4
        for (int k = 0; k < cnt; k++) {
            int s = __shfl_sync(0xffffffffu, myi, k);
            float4 v = *reinterpret_cast<const float4*>(H + (size_t)s * DF + lane * 4);
            acc.x += v.x; acc.y += v.y; acc.z += v.z; acc.w += v.w;
        }
    }
    return acc;
}

__global__ void __launch_bounds__(256) gather_kernel(
    const float* __restrict__ H, float* __restrict__ AGG,
    int node_start, int node_end)
{
    const int w    = node_start + ((blockIdx.x * blockDim.x + threadIdx.x) >> 5);
    const int lane = threadIdx.x & 31;
    if (w >= node_end) return;
    float4 acc = gather_row(w, lane, H);
    *reinterpret_cast<float4*>(AGG + (size_t)w * DF + lane * 4) = acc;
}

// Layer-3 gather fused with head: relu, x_embed, logits, argmax.
__global__ void __launch_bounds__(256) gather_head_kernel(
    const float* __restrict__ H, const float* __restrict__ Wout,
    const float* __restrict__ bout, float* __restrict__ out)
{
    const int w    = (blockIdx.x * blockDim.x + threadIdx.x) >> 5;
    const int lane = threadIdx.x & 31;
    if (w >= NN) return;

    float4 v = gather_row(w, lane, H);
    v.x = fmaxf(v.x, 0.f); v.y = fmaxf(v.y, 0.f);
    v.z = fmaxf(v.z, 0.f); v.w = fmaxf(v.w, 0.f);
    *reinterpret_cast<float4*>(out + (size_t)w * DF + lane * 4) = v;  // x_embed

    float l0, l1, l2;
    {
        float4 w0 = *reinterpret_cast<const float4*>(Wout + 0 * DF + lane * 4);
        float4 w1 = *reinterpret_cast<const float4*>(Wout + 1 * DF + lane * 4);
        float4 w2 = *reinterpret_cast<const float4*>(Wout + 2 * DF + lane * 4);
        l0 = v.x * w0.x + v.y * w0.y + v.z * w0.z + v.w * w0.w;
        l1 = v.x * w1.x + v.y * w1.y + v.z * w1.z + v.w * w1.w;
        l2 = v.x * w2.x + v.y * w2.y + v.z * w2.z + v.w * w2.w;
    }
    #pragma unroll
    for (int off = 16; off > 0; off >>= 1) {
        l0 += __shfl_xor_sync(0xffffffffu, l0, off);
        l1 += __shfl_xor_sync(0xffffffffu, l1, off);
        l2 += __shfl_xor_sync(0xffffffffu, l2, off);
    }
    if (lane == 0) {
        l0 += bout[0]; l1 += bout[1]; l2 += bout[2];
        g_logits[(size_t)w * 3 + 0] = l0;
        g_logits[(size_t)w * 3 + 1] = l1;
        g_logits[(size_t)w * 3 + 2] = l2;
        int am = 0; float best = l0;
        if (l1 > best) { best = l1; am = 1; }
        if (l2 > best) { best = l2; am = 2; }
        out[(size_t)NN * DF + (size_t)MQ * NCLS + w] = (float)am;  // ypred
    }
}

// node_output = logits[node_index]; y_nodepred = ypred[node_index]
__global__ void node_gather_kernel(const int* __restrict__ node_index,
                                   float* __restrict__ out)
{
    int i = blockIdx.x * blockDim.x + threadIdx.x;
    if (i >= MQ) return;
    int n = node_index[i];
    if ((unsigned)n >= NN) n = 0;
    size_t base = (size_t)NN * DF;
    out[base + (size_t)i * 3 + 0] = g_logits[(size_t)n * 3 + 0];
    out[base + (size_t)i * 3 + 1] = g_logits[(size_t)n * 3 + 1];
    out[base + (size_t)i * 3 + 2] = g_logits[(size_t)n * 3 + 2];
    out[base + (size_t)MQ * NCLS + NN + i] = out[base + (size_t)MQ * NCLS + n];
}

// ---------------------------------------------------------------------------
extern "C" void kernel_launch(void* const* d_in, const int* in_sizes, int n_in,
                              void* d_out, int out_size)
{
    const float* x          = (const float*)d_in[0];
    const int*   edges      = (const int*)d_in[1];
    /* d_in[2] node_label: unused (zeros) */
    const int*   node_index = (const int*)d_in[3];
    const float* W1 = (const float*)d_in[4];  const float* b1 = (const float*)d_in[5];
    const float* W2 = (const float*)d_in[6];  const float* b2 = (const float*)d_in[7];
    const float* W3 = (const float*)d_in[8];  const float* b3 = (const float*)d_in[9];
    const float* Wout = (const float*)d_in[10]; const float* bout = (const float*)d_in[11];
    float* out = (float*)d_out;

    float *Ha, *Hb, *A;
    cudaGetSymbolAddress((void**)&Ha, g_Ha);
    cudaGetSymbolAddress((void**)&Hb, g_Hb);
    cudaGetSymbolAddress((void**)&A,  g_A);
    int* degp;
    cudaGetSymbolAddress((void**)&degp, g_deg);

    const int gemm_full = (NN + 127) / 128;           // 391
    const int gemm_c0   = C0 / 128;                   // 196
    const int gemm_c1   = gemm_full - gemm_c0;        // 195
    const int edge_blocks = (EE + 255) / 256;         // 3125
    const int gw0 = (C0 * 32 + 255) / 256;            // chunk0 gather blocks
    const int gw1 = ((NN - C0) * 32 + 255) / 256;     // chunk1 gather blocks
    const int gw_full = ((size_t)NN * 32 + 255) / 256;

    cudaStream_t sd = g_side.s;

    // ---- CSR build on side stream, GEMM-1 (x -> Ha) on main (independent) ----
    cudaEventRecord(g_side.fork, 0);
    cudaStreamWaitEvent(sd, g_side.fork, 0);
    cudaMemsetAsync(degp, 0, NN * sizeof(int), sd);
    hist_kernel<<<edge_blocks, 256, 0, sd>>>(edges);
    scan_kernel<<<1, 1024, 0, sd>>>();
    fill_kernel<<<edge_blocks, 256, 0, sd>>>(edges);
    cudaEventRecord(g_side.join, sd);

    gemm_kernel<false><<<gemm_full, 256>>>(x, W1, b1, Ha, 0);
    cudaStreamWaitEvent(0, g_side.join, 0);

    // ---- boundary 1: gather-1 (Ha -> A) overlapped with GEMM-2 (A -> Hb) ----
    gather_kernel<<<gw0, 256>>>(Ha, A, 0, C0);                    // G0 (main)
    cudaEventRecord(g_side.a0, 0);
    cudaStreamWaitEvent(sd, g_side.a0, 0);
    gather_kernel<<<gw1, 256, 0, sd>>>(Ha, A, C0, NN);            // G1 (side)
    cudaEventRecord(g_side.b0, sd);
    gemm_kernel<true><<<gemm_c0, 256>>>(A, W2, b2, Hb, 0);        // M0 ∥ G1
    cudaStreamWaitEvent(0, g_side.b0, 0);
    gemm_kernel<true><<<gemm_c1, 256>>>(A, W2, b2, Hb, C0);       // M1

    // ---- boundary 2: gather-2 (Hb -> A) overlapped with GEMM-3 (A -> Ha) ----
    gather_kernel<<<gw0, 256>>>(Hb, A, 0, C0);                    // G0 (main)
    cudaEventRecord(g_side.a1, 0);
    cudaStreamWaitEvent(sd, g_side.a1, 0);
    gather_kernel<<<gw1, 256, 0, sd>>>(Hb, A, C0, NN);            // G1 (side)
    cudaEventRecord(g_side.b1, sd);
    gemm_kernel<true><<<gemm_c0, 256>>>(A, W3, b3, Ha, 0);        // M0 ∥ G1
    cudaStreamWaitEvent(0, g_side.b1, 0);
    gemm_kernel<true><<<gemm_c1, 256>>>(A, W3, b3, Ha, C0);       // M1

    // ---- head ----
    gather_head_kernel<<<gw_full, 256>>>(Ha, Wout, bout, out);
    node_gather_kernel<<<(MQ + 255) / 256, 256>>>(node_index, out);
}

// round 15
// speedup vs baseline: 1.0903x; 1.0903x over previous
#include <cuda_runtime.h>

#define NN   50000
#define EE   800000
#define DF   128
#define NCLS 3
#define MQ   10000

// Scratch (static device globals — no runtime allocation).
__device__ __align__(16) float g_H[(size_t)NN * DF];
__device__ __align__(16) float g_A[(size_t)NN * DF];
__device__ __align__(16) float g_logits[(size_t)NN * NCLS];
__device__ int g_deg[NN];
__device__ int g_off[NN];
__device__ int g_rank[EE];
__device__ int g_csr[EE];

// Side stream + fork/join events, created at static-init.
struct SideStream {
    cudaStream_t s;
    cudaEvent_t  fork, join;
    SideStream() {
        cudaStreamCreateWithFlags(&s, cudaStreamNonBlocking);
        cudaEventCreateWithFlags(&fork, cudaEventDisableTiming);
        cudaEventCreateWithFlags(&join, cudaEventDisableTiming);
    }
};
static SideStream g_side;

// ---------------------------------------------------------------------------
// Packed f32x2 helpers (Blackwell sm_100a+)
// ---------------------------------------------------------------------------
__device__ __forceinline__ unsigned long long splat2(float v)
{
    unsigned long long r;
    asm("mov.b64 %0, {%1, %1};" : "=l"(r) : "f"(v));
    return r;
}
__device__ __forceinline__ void fma2(unsigned long long& d,
                                     unsigned long long a, unsigned long long b)
{
    asm("fma.rn.f32x2 %0, %1, %2, %0;" : "+l"(d) : "l"(a), "l"(b));
}
__device__ __forceinline__ void unpack2(unsigned long long v, float& lo, float& hi)
{
    asm("mov.b64 {%0, %1}, %2;" : "=f"(lo), "=f"(hi) : "l"(v));
}

// ---------------------------------------------------------------------------
// CSR build: memset(deg) -> histogram(dst) capturing per-edge rank -> scan ->
// fill (NO atomics in fill: position = off[dst] + rank[e])
// ---------------------------------------------------------------------------
__global__ void hist_kernel(const int* __restrict__ edges)
{
    int e = blockIdx.x * blockDim.x + threadIdx.x;
    if (e >= EE) return;
    int dst = edges[EE + e];
    int r = 0;
    if ((unsigned)dst < NN) r = atomicAdd(&g_deg[dst], 1);
    g_rank[e] = r;
}

__global__ void __launch_bounds__(1024) scan_kernel()
{
    __shared__ int sh[1024];
    const int T = 1024;
    const int CH = (NN + T - 1) / T;          // 49
    int t = threadIdx.x;
    int start = t * CH;
    int end   = min(start + CH, NN);

    int s = 0;
    for (int i = start; i < end; i++) s += g_deg[i];
    sh[t] = s;
    __syncthreads();

    for (int off = 1; off < T; off <<= 1) {
        int v = (t >= off) ? sh[t - off] : 0;
        __syncthreads();
        sh[t] += v;
        __syncthreads();
    }
    int run = sh[t] - s;   // exclusive prefix for this thread's chunk
    for (int i = start; i < end; i++) {
        g_off[i] = run;
        run += g_deg[i];
    }
}

__global__ void fill_kernel(const int* __restrict__ edges)
{
    int e = blockIdx.x * blockDim.x + threadIdx.x;
    if (e >= EE) return;
    int dst = edges[EE + e];
    int src = edges[e];
    if ((unsigned)dst >= NN || (unsigned)src >= NN) return;
    g_csr[g_off[dst] + g_rank[e]] = src;
}

// ---------------------------------------------------------------------------
// GEMM: H[r][n] = sum_k act(X[r][k]) * W[n][k] + b[n]
// BM=128, BN=128, BK=32; 256 threads as 8 warps x 32 lanes; thread tile
// 16 rows x 4 cols (8 row-pairs x 4 cols of packed f32x2 FMAs).
//  - warp == fixed tr -> A-fragment LDS are warp-uniform broadcasts
//  - B-fragment &Ws[k][tc*4]: 32 lanes x 16B contiguous -> conflict-free
//  - only 4 splat MOVs per warp-k (each feeds 8 fma2)
// __launch_bounds__(256,2). Smem 33.8 KB/CTA.
// ---------------------------------------------------------------------------
#define LDP 132   // row stride (floats): 528 B = 33*16 (ulonglong2-safe)

template <bool RELU_IN>
__global__ void __launch_bounds__(256, 2) gemm_kernel(
    const float* __restrict__ X, const float* __restrict__ W,
    const float* __restrict__ bias, float* __restrict__ H)
{
    __shared__ __align__(16) float Xs[32][LDP];   // Xs[k][m]
    __shared__ __align__(16) float Ws[32][LDP];   // Ws[k][n] = W[n][k_global]

    const int tid  = threadIdx.x;
    const int row0 = blockIdx.x * 128;
    const int tr   = tid >> 5;      // warp id: rows tr*16..tr*16+15
    const int tc   = tid & 31;      // lane:   cols tc*4..tc*4+3

    unsigned long long acc2[8][4];  // [row-pair][col]
    #pragma unroll
    for (int i = 0; i < 8; i++)
        #pragma unroll
        for (int j = 0; j < 4; j++) acc2[i][j] = 0ull;

    for (int kb = 0; kb < DF; kb += 32) {
        #pragma unroll
        for (int i = 0; i < 4; i++) {
            int idx = tid + i * 256;          // 0..1023
            int r   = idx >> 3;               // 0..127
            int c4  = idx & 7;                // 0..7
            int gr  = row0 + r;
            float4 v = make_float4(0.f, 0.f, 0.f, 0.f);
            if (gr < NN)
                v = *reinterpret_cast<const float4*>(X + (size_t)gr * DF + kb + c4 * 4);
            if (RELU_IN) {
                v.x = fmaxf(v.x, 0.f); v.y = fmaxf(v.y, 0.f);
                v.z = fmaxf(v.z, 0.f); v.w = fmaxf(v.w, 0.f);
            }
            Xs[c4 * 4 + 0][r] = v.x; Xs[c4 * 4 + 1][r] = v.y;
            Xs[c4 * 4 + 2][r] = v.z; Xs[c4 * 4 + 3][r] = v.w;
        }
        #pragma unroll
        for (int i = 0; i < 4; i++) {
            int idx = tid + i * 256;
            int n   = idx >> 3;               // 0..127
            int c4  = idx & 7;
            float4 v = *reinterpret_cast<const float4*>(W + (size_t)n * DF + kb + c4 * 4);
            Ws[c4 * 4 + 0][n] = v.x; Ws[c4 * 4 + 1][n] = v.y;
            Ws[c4 * 4 + 2][n] = v.z; Ws[c4 * 4 + 3][n] = v.w;
        }
        __syncthreads();

        #pragma unroll
        for (int k = 0; k < 32; k++) {
            // A: 16 rows = 8 packed pairs; warp-uniform address (broadcast).
            ulonglong2 a01 = *reinterpret_cast<const ulonglong2*>(&Xs[k][tr * 16]);
            ulonglong2 a23 = *reinterpret_cast<const ulonglong2*>(&Xs[k][tr * 16 + 4]);
            ulonglong2 a45 = *reinterpret_cast<const ulonglong2*>(&Xs[k][tr * 16 + 8]);
            ulonglong2 a67 = *reinterpret_cast<const ulonglong2*>(&Xs[k][tr * 16 + 12]);
            // B: 4 cols, 16B/lane contiguous across the warp (conflict-free).
            float4 b = *reinterpret_cast<const float4*>(&Ws[k][tc * 4]);

            unsigned long long ap[8] = {a01.x, a01.y, a23.x, a23.y,
                                        a45.x, a45.y, a67.x, a67.y};
            unsigned long long bs[4];
            bs[0] = splat2(b.x); bs[1] = splat2(b.y);
            bs[2] = splat2(b.z); bs[3] = splat2(b.w);

            #pragma unroll
            for (int i = 0; i < 8; i++)
                #pragma unroll
                for (int j = 0; j < 4; j++)
                    fma2(acc2[i][j], ap[i], bs[j]);
        }
        __syncthreads();
    }

    float bn[4];
    #pragma unroll
    for (int j = 0; j < 4; j++) bn[j] = bias[tc * 4 + j];

    #pragma unroll
    for (int i2 = 0; i2 < 8; i2++) {
        float lo[4], hi[4];
        #pragma unroll
        for (int j = 0; j < 4; j++) unpack2(acc2[i2][j], lo[j], hi[j]);

        int gr0 = row0 + tr * 16 + 2 * i2;
        if (gr0 < NN) {
            float4 v;
            v.x = lo[0] + bn[0]; v.y = lo[1] + bn[1];
            v.z = lo[2] + bn[2]; v.w = lo[3] + bn[3];
            *reinterpret_cast<float4*>(H + (size_t)gr0 * DF + tc * 4) = v;
        }
        int gr1 = gr0 + 1;
        if (gr1 < NN) {
            float4 v;
            v.x = hi[0] + bn[0]; v.y = hi[1] + bn[1];
            v.z = hi[2] + bn[2]; v.w = hi[3] + bn[3];
            *reinterpret_cast<float4*>(H + (size_t)gr1 * DF + tc * 4) = v;
        }
    }
}

// ---------------------------------------------------------------------------
// Gather segment-sum: AGG[n] = H[n] + sum_{s in csr[n]} H[s]. One warp/node.
// ---------------------------------------------------------------------------
__device__ __forceinline__ float4 gather_row(int node, int lane,
                                             const float* __restrict__ H)
{
    int start = g_off[node];
    int deg   = g_deg[node];

    float4 acc = *reinterpret_cast<const float4*>(H + (size_t)node * DF + lane * 4);

    for (int j = 0; j < deg; j += 32) {
        int rem  = deg - j;
        int cnt  = rem < 32 ? rem : 32;
        int myi  = (lane < cnt) ? g_csr[start + j + lane] : 0;
        #pragma unroll 4
        for (int k = 0; k < cnt; k++) {
            int s = __shfl_sync(0xffffffffu, myi, k);
            float4 v = *reinterpret_cast<const float4*>(H + (size_t)s * DF + lane * 4);
            acc.x += v.x; acc.y += v.y; acc.z += v.z; acc.w += v.w;
        }
    }
    return acc;
}

__global__ void __launch_bounds__(256) gather_kernel(
    const float* __restrict__ H, float* __restrict__ AGG)
{
    const int w    = (blockIdx.x * blockDim.x + threadIdx.x) >> 5;
    const int lane = threadIdx.x & 31;
    if (w >= NN) return;
    float4 acc = gather_row(w, lane, H);
    *reinterpret_cast<float4*>(AGG + (size_t)w * DF + lane * 4) = acc;
}

// Layer-3 gather fused with head: relu, x_embed, logits, argmax.
__global__ void __launch_bounds__(256) gather_head_kernel(
    const float* __restrict__ H, const float* __restrict__ Wout,
    const float* __restrict__ bout, float* __restrict__ out)
{
    const int w    = (blockIdx.x * blockDim.x + threadIdx.x) >> 5;
    const int lane = threadIdx.x & 31;
    if (w >= NN) return;

    float4 v = gather_row(w, lane, H);
    v.x = fmaxf(v.x, 0.f); v.y = fmaxf(v.y, 0.f);
    v.z = fmaxf(v.z, 0.f); v.w = fmaxf(v.w, 0.f);
    *reinterpret_cast<float4*>(out + (size_t)w * DF + lane * 4) = v;  // x_embed

    float l0, l1, l2;
    {
        float4 w0 = *reinterpret_cast<const float4*>(Wout + 0 * DF + lane * 4);
        float4 w1 = *reinterpret_cast<const float4*>(Wout + 1 * DF + lane * 4);
        float4 w2 = *reinterpret_cast<const float4*>(Wout + 2 * DF + lane * 4);
        l0 = v.x * w0.x + v.y * w0.y + v.z * w0.z + v.w * w0.w;
        l1 = v.x * w1.x + v.y * w1.y + v.z * w1.z + v.w * w1.w;
        l2 = v.x * w2.x + v.y * w2.y + v.z * w2.z + v.w * w2.w;
    }
    #pragma unroll
    for (int off = 16; off > 0; off >>= 1) {
        l0 += __shfl_xor_sync(0xffffffffu, l0, off);
        l1 += __shfl_xor_sync(0xffffffffu, l1, off);
        l2 += __shfl_xor_sync(0xffffffffu, l2, off);
    }
    if (lane == 0) {
        l0 += bout[0]; l1 += bout[1]; l2 += bout[2];
        g_logits[(size_t)w * 3 + 0] = l0;
        g_logits[(size_t)w * 3 + 1] = l1;
        g_logits[(size_t)w * 3 + 2] = l2;
        int am = 0; float best = l0;
        if (l1 > best) { best = l1; am = 1; }
        if (l2 > best) { best = l2; am = 2; }
        out[(size_t)NN * DF + (size_t)MQ * NCLS + w] = (float)am;  // ypred
    }
}

// node_output = logits[node_index]; y_nodepred = ypred[node_index]
__global__ void node_gather_kernel(const int* __restrict__ node_index,
                                   float* __restrict__ out)
{
    int i = blockIdx.x * blockDim.x + threadIdx.x;
    if (i >= MQ) return;
    int n = node_index[i];
    if ((unsigned)n >= NN) n = 0;
    size_t base = (size_t)NN * DF;
    out[base + (size_t)i * 3 + 0] = g_logits[(size_t)n * 3 + 0];
    out[base + (size_t)i * 3 + 1] = g_logits[(size_t)n * 3 + 1];
    out[base + (size_t)i * 3 + 2] = g_logits[(size_t)n * 3 + 2];
    out[base + (size_t)MQ * NCLS + NN + i] = out[base + (size_t)MQ * NCLS + n];
}

// ---------------------------------------------------------------------------
extern "C" void kernel_launch(void* const* d_in, const int* in_sizes, int n_in,
                              void* d_out, int out_size)
{
    const float* x          = (const float*)d_in[0];
    const int*   edges      = (const int*)d_in[1];
    /* d_in[2] node_label: unused (zeros) */
    const int*   node_index = (const int*)d_in[3];
    const float* W1 = (const float*)d_in[4];  const float* b1 = (const float*)d_in[5];
    const float* W2 = (const float*)d_in[6];  const float* b2 = (const float*)d_in[7];
    const float* W3 = (const float*)d_in[8];  const float* b3 = (const float*)d_in[9];
    const float* Wout = (const float*)d_in[10]; const float* bout = (const float*)d_in[11];
    float* out = (float*)d_out;

    float *H, *A;
    cudaGetSymbolAddress((void**)&H, g_H);
    cudaGetSymbolAddress((void**)&A, g_A);
    int* degp;
    cudaGetSymbolAddress((void**)&degp, g_deg);

    const int gemm_blocks = (NN + 127) / 128;               // 391
    const int edge_blocks = (EE + 255) / 256;               // 3125
    const int warp_blocks = ((size_t)NN * 32 + 255) / 256;  // 6250

    // Fork: CSR build on side stream, GEMM-1 on main stream (independent).
    cudaEventRecord(g_side.fork, 0);
    cudaStreamWaitEvent(g_side.s, g_side.fork, 0);

    cudaMemsetAsync(degp, 0, NN * sizeof(int), g_side.s);
    hist_kernel<<<edge_blocks, 256, 0, g_side.s>>>(edges);
    scan_kernel<<<1, 1024, 0, g_side.s>>>();
    fill_kernel<<<edge_blocks, 256, 0, g_side.s>>>(edges);
    cudaEventRecord(g_side.join, g_side.s);

    gemm_kernel<false><<<gemm_blocks, 256>>>(x, W1, b1, H);   // main stream

    // Join: gather-1 needs both GEMM-1 and the CSR.
    cudaStreamWaitEvent(0, g_side.join, 0);

    gather_kernel<<<warp_blocks, 256>>>(H, A);
    // Layer 2 (relu on read)
    gemm_kernel<true><<<gemm_blocks, 256>>>(A, W2, b2, H);
    gather_kernel<<<warp_blocks, 256>>>(H, A);
    // Layer 3 + fused head
    gemm_kernel<true><<<gemm_blocks, 256>>>(A, W3, b3, H);
    gather_head_kernel<<<warp_blocks, 256>>>(H, Wout, bout, out);

    node_gather_kernel<<<(MQ + 255) / 256, 256>>>(node_index, out);
}